// round 10
// baseline (speedup 1.0000x reference)
#include <cuda_runtime.h>

#define NN    2048
#define DIN   128
#define HH    256
#define DEMB  64
#define NSTRIP 8
#define STRIPJ (NN / NSTRIP)   // 256
#define BI    64
#define BJ    64

// -------- device scratch (no allocations allowed) --------
__device__ __align__(16) float g_outx[NN * HH];             // 2 MB
__device__ __align__(16) float g_emb[NN * DEMB];            // 512 KB
__device__ __align__(16) float g_sq[NN];                    // 8 KB
__device__ __align__(16) float g_xlast[NN * DIN];           // 1 MB
__device__ __align__(16) float g_ypart[NSTRIP * NN * DIN];  // 8 MB
__device__ __align__(16) float g_degpart[NSTRIP * NN];      // 64 KB

// -------- packed fp32x2 helpers (exact fp32, 2 FMA / instr) --------
typedef unsigned long long ull;
__device__ __forceinline__ ull pk2(float a, float b) {
    ull r; asm("mov.b64 %0, {%1, %2};" : "=l"(r) : "f"(a), "f"(b)); return r;
}
__device__ __forceinline__ void fma2(ull& d, ull a, ull b) {
    asm("fma.rn.f32x2 %0, %1, %2, %0;" : "+l"(d) : "l"(a), "l"(b));
}
__device__ __forceinline__ float2 upk(ull v) {
    float2 f; asm("mov.b64 {%0, %1}, %2;" : "=f"(f.x), "=f"(f.y) : "l"(v)); return f;
}
__device__ __forceinline__ float sigmoidf(float z) {
    return 1.0f / (1.0f + __expf(-z));
}

// ============================================================
// 64x64 output tile of C = [relu](A @ B + bias)
// A [M,LDA] row-major, B [LDA-k domain, LDB] row-major.
// kB-style: smem-staged AT (k-major) + B, 4x4/thread, FFMA2.
// ============================================================
template<bool RELU, int KTOT, int LDA, int LDB>
__device__ __forceinline__ void gemm_tile64(
    const float* __restrict__ A, const float* __restrict__ B,
    const float* __restrict__ bias, float* __restrict__ C,
    int i0, int n0, float* sm)
{
    float* AT = sm;            // [64][68]  AT[k][r]
    float* Bs = sm + 64 * 68;  // [64][68]  Bs[k][c]
    const int t  = threadIdx.x;
    const int r0 = (t >> 4) * 4;
    const int c0 = (t & 15) * 4;

    ull acc[4][2];
    #pragma unroll
    for (int r = 0; r < 4; r++) { acc[r][0] = 0ULL; acc[r][1] = 0ULL; }

    #pragma unroll
    for (int kc = 0; kc < KTOT; kc += 64) {
        __syncthreads();
        #pragma unroll
        for (int idx = t; idx < 64 * 64; idx += 256) {
            const int kk = idx & 63, r = idx >> 6;
            AT[kk * 68 + r] = A[(size_t)(i0 + r) * LDA + kc + kk];
        }
        #pragma unroll
        for (int idx = t; idx < 64 * 64; idx += 256) {
            const int c = idx & 63, kk = idx >> 6;
            Bs[kk * 68 + c] = B[(size_t)(kc + kk) * LDB + n0 + c];
        }
        __syncthreads();

        #pragma unroll 4
        for (int k = 0; k < 64; k++) {
            const float4 ai = *(const float4*)&AT[k * 68 + r0];
            const float4 bj = *(const float4*)&Bs[k * 68 + c0];
            const ull b01 = pk2(bj.x, bj.y);
            const ull b23 = pk2(bj.z, bj.w);
            ull aa;
            aa = pk2(ai.x, ai.x); fma2(acc[0][0], aa, b01); fma2(acc[0][1], aa, b23);
            aa = pk2(ai.y, ai.y); fma2(acc[1][0], aa, b01); fma2(acc[1][1], aa, b23);
            aa = pk2(ai.z, ai.z); fma2(acc[2][0], aa, b01); fma2(acc[2][1], aa, b23);
            aa = pk2(ai.w, ai.w); fma2(acc[3][0], aa, b01); fma2(acc[3][1], aa, b23);
        }
    }

    const float4 bb = *(const float4*)(bias + n0 + c0);
    #pragma unroll
    for (int rr = 0; rr < 4; rr++) {
        const float2 g0 = upk(acc[rr][0]);
        const float2 g1 = upk(acc[rr][1]);
        float4 w;
        w.x = g0.x + bb.x; w.y = g0.y + bb.y;
        w.z = g1.x + bb.z; w.w = g1.y + bb.w;
        if (RELU) {
            w.x = fmaxf(w.x, 0.f); w.y = fmaxf(w.y, 0.f);
            w.z = fmaxf(w.z, 0.f); w.w = fmaxf(w.w, 0.f);
        }
        *(float4*)(C + (size_t)(i0 + r0 + rr) * LDB + n0 + c0) = w;
    }
}

// ============================================================
// kA13: blocks 0..127 -> outx = relu(x@W0+b0)   [2048,256]
//       blocks 128..191 -> xlast = x@W2+b2      [2048,128]
// ============================================================
__global__ void __launch_bounds__(256) kA13(
    const float* __restrict__ x,
    const float* __restrict__ W0, const float* __restrict__ b0,
    const float* __restrict__ W2, const float* __restrict__ b2)
{
    __shared__ float sm[2 * 64 * 68];
    const int bid = blockIdx.x;
    if (bid < 128) {
        gemm_tile64<true, DIN, DIN, HH>(x, W0, b0, g_outx,
                                        (bid >> 2) * 64, (bid & 3) * 64, sm);
    } else {
        const int b = bid - 128;
        gemm_tile64<false, DIN, DIN, DIN>(x, W2, b2, g_xlast,
                                          (b >> 1) * 64, (b & 1) * 64, sm);
    }
}

// ============================================================
// kA2: emb = relu(outx@W1+b1)  [2048,64]; sq in epilogue.
// grid 64, tile 32x64, thread = 2 rows x 4 cols, K=256.
// ============================================================
__global__ void __launch_bounds__(256) kA2(
    const float* __restrict__ W1, const float* __restrict__ b1)
{
    __shared__ float AT[64 * 36];   // AT[k][r], 32 rows + pad
    __shared__ float Bs[64 * 68];   // Bs[k][c]
    __shared__ float red[32 * 16];

    const int t  = threadIdx.x;
    const int i0 = blockIdx.x * 32;
    const int r0 = (t >> 4) * 2;
    const int c0 = (t & 15) * 4;

    ull acc[4] = {0ULL, 0ULL, 0ULL, 0ULL};   // acc[c] = (row r0, row r0+1)

    #pragma unroll
    for (int kc = 0; kc < HH; kc += 64) {
        __syncthreads();
        #pragma unroll
        for (int idx = t; idx < 64 * 32; idx += 256) {
            const int kk = idx & 63, r = idx >> 6;
            AT[kk * 36 + r] = g_outx[(size_t)(i0 + r) * HH + kc + kk];
        }
        #pragma unroll
        for (int idx = t; idx < 64 * 64; idx += 256) {
            const int c = idx & 63, kk = idx >> 6;
            Bs[kk * 68 + c] = W1[(size_t)(kc + kk) * DEMB + c];
        }
        __syncthreads();

        #pragma unroll 4
        for (int k = 0; k < 64; k++) {
            const ull x2 = *(const ull*)&AT[k * 36 + r0];
            const float4 bj = *(const float4*)&Bs[k * 68 + c0];
            fma2(acc[0], x2, pk2(bj.x, bj.x));
            fma2(acc[1], x2, pk2(bj.y, bj.y));
            fma2(acc[2], x2, pk2(bj.z, bj.z));
            fma2(acc[3], x2, pk2(bj.w, bj.w));
        }
    }

    // epilogue: bias + relu, write emb, sq partials
    const float4 bb = *(const float4*)(b1 + c0);
    const float bbv[4] = {bb.x, bb.y, bb.z, bb.w};
    float2 v[4];
    float s0 = 0.f, s1 = 0.f;
    #pragma unroll
    for (int c = 0; c < 4; c++) {
        v[c] = upk(acc[c]);
        v[c].x = fmaxf(v[c].x + bbv[c], 0.f);
        v[c].y = fmaxf(v[c].y + bbv[c], 0.f);
        s0 = fmaf(v[c].x, v[c].x, s0);
        s1 = fmaf(v[c].y, v[c].y, s1);
    }
    *(float4*)(g_emb + (size_t)(i0 + r0) * DEMB + c0) =
        make_float4(v[0].x, v[1].x, v[2].x, v[3].x);
    *(float4*)(g_emb + (size_t)(i0 + r0 + 1) * DEMB + c0) =
        make_float4(v[0].y, v[1].y, v[2].y, v[3].y);

    red[r0 * 16 + (t & 15)]       = s0;
    red[(r0 + 1) * 16 + (t & 15)] = s1;
    __syncthreads();
    if (t < 32) {
        float s = 0.f;
        #pragma unroll
        for (int g = 0; g < 16; g++) s += red[t * 16 + g];
        g_sq[i0 + t] = s;
    }
}

// ============================================================
// Kernel B: 64 i-rows x 256 j-cols strip of A per block.
//  GEMM1 (4x4/thread, FFMA2) -> sigmoid+eye epilogue -> adj +
//  GEMM2 (2 rows x 16 cols/thread, FFMA2, conflict-free cols).
// grid (8, 32) = 256 blocks, 2 blocks/SM.
// ============================================================
__global__ void __launch_bounds__(256, 2) kB(
    const float* __restrict__ tempp,
    const float* __restrict__ thetap,
    float* __restrict__ adj_out)
{
    extern __shared__ float sm[];
    float* embIs = sm;                    // [64][68] k-major
    float* embJs = embIs + 64 * 68;       // [64][68] k-major
    float* xls   = embJs + 64 * 68;       // [64][132] j-major, padded
    float* As    = xls + 64 * 132;        // [64][68]
    float* sqJs  = As + 64 * 68;          // [64]
    float* degsh = sqJs + 64;             // [64][16]

    const int t  = threadIdx.x;
    const int s  = blockIdx.x;            // strip
    const int i0 = blockIdx.y * BI;
    const int jstart = s * STRIPJ;

    const float c1 = 1.0f + *tempp;
    const float c2 = 5.0f + *thetap;

    // stage embI transposed (k-major)
    #pragma unroll
    for (int idx = t; idx < BI * DEMB; idx += 256) {
        const int k = idx & 63, r = idx >> 6;
        embIs[k * 68 + r] = g_emb[(i0 + r) * DEMB + k];
    }

    // GEMM1 coords: 4 rows x 4 cols per thread
    const int r0 = (t >> 4) * 4;
    const int c0 = (t & 15) * 4;
    const float4 sqI = *(const float4*)&g_sq[i0 + r0];
    float degA[4] = {0.f, 0.f, 0.f, 0.f};

    // GEMM2 coords: rows {2q, 2q+1}, cols {g*4 + 32u + 0..3}
    const int q = t >> 3;
    const int g = t & 7;
    ull yac[2][8];
    #pragma unroll
    for (int r = 0; r < 2; r++)
        #pragma unroll
        for (int p = 0; p < 8; p++) yac[r][p] = 0ULL;

    for (int cj = 0; cj < STRIPJ / BJ; cj++) {
        const int jb = jstart + cj * BJ;
        __syncthreads();   // prev-iter readers done before overwrite

        // stage embJ transposed
        #pragma unroll
        for (int idx = t; idx < BJ * DEMB; idx += 256) {
            const int k = idx & 63, jl = idx >> 6;
            embJs[k * 68 + jl] = g_emb[(jb + jl) * DEMB + k];
        }
        if (t < BJ) sqJs[t] = g_sq[jb + t];
        // stage x_last chunk [64][132-padded] via float4
        {
            const float4* src = (const float4*)(g_xlast + (size_t)jb * DIN);
            #pragma unroll
            for (int idx = t; idx < BJ * DIN / 4; idx += 256) {
                const int row = idx >> 5, c4 = idx & 31;
                *(float4*)&xls[row * 132 + c4 * 4] = src[idx];
            }
        }
        __syncthreads();

        // ---- GEMM1: 4x4 per thread over k=64, packed j-pairs ----
        ull acc[4][2];
        #pragma unroll
        for (int r = 0; r < 4; r++) { acc[r][0] = 0ULL; acc[r][1] = 0ULL; }
        #pragma unroll 4
        for (int k = 0; k < DEMB; k++) {
            const float4 ai = *(const float4*)&embIs[k * 68 + r0];
            const float4 bj = *(const float4*)&embJs[k * 68 + c0];
            const ull b01 = pk2(bj.x, bj.y);
            const ull b23 = pk2(bj.z, bj.w);
            ull aa;
            aa = pk2(ai.x, ai.x); fma2(acc[0][0], aa, b01); fma2(acc[0][1], aa, b23);
            aa = pk2(ai.y, ai.y); fma2(acc[1][0], aa, b01); fma2(acc[1][1], aa, b23);
            aa = pk2(ai.z, ai.z); fma2(acc[2][0], aa, b01); fma2(acc[2][1], aa, b23);
            aa = pk2(ai.w, ai.w); fma2(acc[3][0], aa, b01); fma2(acc[3][1], aa, b23);
        }

        // ---- epilogue: sigmoid + eye, write adj, stash A tile, deg ----
        {
            const float4 sqJ = *(const float4*)&sqJs[c0];
            const int jbase = jb + c0;
            const float si[4] = {sqI.x, sqI.y, sqI.z, sqI.w};
            #pragma unroll
            for (int rr = 0; rr < 4; rr++) {
                const float2 g0 = upk(acc[rr][0]);
                const float2 g1 = upk(acc[rr][1]);
                const float zi = si[rr];
                const int i = i0 + r0 + rr;
                float4 w;
                w.x = sigmoidf(fmaf(c1, 2.f * g0.x - zi - sqJ.x, c2));
                w.y = sigmoidf(fmaf(c1, 2.f * g0.y - zi - sqJ.y, c2));
                w.z = sigmoidf(fmaf(c1, 2.f * g1.x - zi - sqJ.z, c2));
                w.w = sigmoidf(fmaf(c1, 2.f * g1.y - zi - sqJ.w, c2));
                if (i == jbase)     w.x += 1.f;
                if (i == jbase + 1) w.y += 1.f;
                if (i == jbase + 2) w.z += 1.f;
                if (i == jbase + 3) w.w += 1.f;
                degA[rr] += (w.x + w.y) + (w.z + w.w);
                *(float4*)(adj_out + (size_t)i * NN + jbase) = w;
                *(float4*)&As[(r0 + rr) * 68 + c0] = w;
            }
        }
        __syncthreads();

        // ---- GEMM2: y[64][128] += A[64][64] @ xls[64][128] ----
        #pragma unroll 4
        for (int c = 0; c < BJ; c++) {
            const float a0 = As[(2 * q) * 68 + c];
            const float a1 = As[(2 * q + 1) * 68 + c];
            const ull A0 = pk2(a0, a0);
            const ull A1 = pk2(a1, a1);
            #pragma unroll
            for (int u = 0; u < 4; u++) {
                const float4 xv = *(const float4*)&xls[c * 132 + g * 4 + 32 * u];
                const ull x01 = pk2(xv.x, xv.y);
                const ull x23 = pk2(xv.z, xv.w);
                fma2(yac[0][2 * u],     A0, x01);
                fma2(yac[0][2 * u + 1], A0, x23);
                fma2(yac[1][2 * u],     A1, x01);
                fma2(yac[1][2 * u + 1], A1, x23);
            }
        }
    }

    // write y partials
    #pragma unroll
    for (int r = 0; r < 2; r++) {
        float* base = g_ypart + ((size_t)s * NN + i0 + 2 * q + r) * DIN;
        #pragma unroll
        for (int u = 0; u < 4; u++) {
            const float2 p0 = upk(yac[r][2 * u]);
            const float2 p1 = upk(yac[r][2 * u + 1]);
            *(float4*)(base + g * 4 + 32 * u) = make_float4(p0.x, p0.y, p1.x, p1.y);
        }
    }

    // deg reduction (deterministic)
    #pragma unroll
    for (int rr = 0; rr < 4; rr++)
        degsh[(r0 + rr) * 16 + (t & 15)] = degA[rr];
    __syncthreads();
    if (t < BI) {
        float sdeg = 0.f;
        #pragma unroll
        for (int gg = 0; gg < 16; gg++) sdeg += degsh[t * 16 + gg];
        g_degpart[s * NN + i0 + t] = sdeg;
    }
}

// ============================================================
// Kernel C: out = relu( (sum_s y_part) / (sum_s deg_part) )
// ============================================================
__global__ void __launch_bounds__(256) kC(float* __restrict__ out)
{
    const int idx = blockIdx.x * 256 + threadIdx.x;  // < N*DIN
    const int i = idx >> 7;
    const int d = idx & 127;
    float deg = 0.f;
    #pragma unroll
    for (int s = 0; s < NSTRIP; s++) deg += g_degpart[s * NN + i];
    float y = 0.f;
    #pragma unroll
    for (int s = 0; s < NSTRIP; s++)
        y += g_ypart[((size_t)s * NN + i) * DIN + d];
    out[idx] = fmaxf(y / deg, 0.f);
}

// ============================================================
extern "C" void kernel_launch(void* const* d_in, const int* in_sizes, int n_in,
                              void* d_out, int out_size)
{
    const float* x     = (const float*)d_in[0];
    // d_in[1] = adj : unused (only its shape matters in the reference)
    const float* W0    = (const float*)d_in[2];
    const float* b0    = (const float*)d_in[3];
    const float* W1    = (const float*)d_in[4];
    const float* b1    = (const float*)d_in[5];
    const float* W2    = (const float*)d_in[6];
    const float* b2    = (const float*)d_in[7];
    const float* temp  = (const float*)d_in[8];
    const float* theta = (const float*)d_in[9];

    float* out     = (float*)d_out;          // [N, DIN] first
    float* adj_out = out + NN * DIN;         // then [N*N] adjacency

    kA13<<<192, 256>>>(x, W0, b0, W2, b2);
    kA2<<<NN / 32, 256>>>(W1, b1);

    const int smemB = (64 * 68 + 64 * 68 + 64 * 132 + 64 * 68 + 64 + 64 * 16) * 4;
    cudaFuncSetAttribute(kB, cudaFuncAttributeMaxDynamicSharedMemorySize, smemB);
    dim3 gB(NSTRIP, NN / BI);
    kB<<<gB, 256, smemB>>>(temp, theta, adj_out);

    kC<<<NN * DIN / 256, 256>>>(out);
}